// round 2
// baseline (speedup 1.0000x reference)
#include <cuda_runtime.h>

#define H 512
#define W 512
#define NPLANES 12          // B*C = 4*3
#define KS 5
#define PAD 2
#define BX 32
#define BY 8
#define TILE_W (BX + 2*PAD)   // 36
#define TILE_H (BY + 2*PAD)   // 12

__global__ __launch_bounds__(BX * BY)
void bilateral_kernel(const float* __restrict__ x,
                      const float* __restrict__ weight_space,
                      float* __restrict__ out)
{
    __shared__ float tile[TILE_H][TILE_W];
    __shared__ float ws[KS * KS];

    const int plane = blockIdx.z;                  // 0..11
    const float* xp = x + (size_t)plane * H * W;

    const int bx = blockIdx.x * BX;
    const int by = blockIdx.y * BY;
    const int tid = threadIdx.y * BX + threadIdx.x;

    if (tid < KS * KS) ws[tid] = weight_space[tid];

    // Cooperative tile load with reflect padding (jnp 'reflect': -1 -> 1, H -> H-2)
    #pragma unroll
    for (int i = tid; i < TILE_H * TILE_W; i += BX * BY) {
        int ty = i / TILE_W;
        int tx = i - ty * TILE_W;
        int gy = by + ty - PAD;
        int gx = bx + tx - PAD;
        gy = (gy < 0) ? -gy : ((gy >= H) ? (2 * H - 2 - gy) : gy);
        gx = (gx < 0) ? -gx : ((gx >= W) ? (2 * W - 2 - gx) : gx);
        tile[ty][tx] = xp[gy * W + gx];
    }
    __syncthreads();

    const float c = tile[threadIdx.y + PAD][threadIdx.x + PAD];

    float num = 0.0f;
    float den = 0.0f;
    #pragma unroll
    for (int i = 0; i < KS; i++) {
        #pragma unroll
        for (int j = 0; j < KS; j++) {
            float p = tile[threadIdx.y + i][threadIdx.x + j];
            float d = p - c;
            // wd = exp(-d^2 / (2*SIGMA_DENSITY^2)), SIGMA_DENSITY = 1
            float wd = __expf(-0.5f * d * d) * ws[i * KS + j];
            num = fmaf(wd, p, num);
            den += wd;
        }
    }

    out[(size_t)plane * H * W + (by + threadIdx.y) * W + (bx + threadIdx.x)] = num / den;
}

extern "C" void kernel_launch(void* const* d_in, const int* in_sizes, int n_in,
                              void* d_out, int out_size)
{
    const float* x  = (const float*)d_in[0];        // [4,3,512,512] fp32
    const float* ws = (const float*)d_in[1];        // [5,5] fp32
    float* out = (float*)d_out;

    dim3 block(BX, BY);
    dim3 grid(W / BX, H / BY, NPLANES);             // 16 x 64 x 12 = 12288 CTAs
    bilateral_kernel<<<grid, block>>>(x, ws, out);
}

// round 3
// speedup vs baseline: 1.0007x; 1.0007x over previous
#include <cuda_runtime.h>

#define H 512
#define W 512
#define NPLANES 12          // B*C = 4*3
#define KS 5
#define PAD 2
#define BX 32
#define BY 8
#define TILE_W (BX + 2*PAD)   // 36
#define TILE_H (BY + 2*PAD)   // 12

__global__ __launch_bounds__(BX * BY)
void bilateral_kernel(const float* __restrict__ x,
                      const float* __restrict__ weight_space,
                      float* __restrict__ out)
{
    __shared__ float tile[TILE_H][TILE_W];
    __shared__ float ws[KS * KS];

    const int plane = blockIdx.z;                  // 0..11
    const float* xp = x + (size_t)plane * H * W;

    const int bx = blockIdx.x * BX;
    const int by = blockIdx.y * BY;
    const int tid = threadIdx.y * BX + threadIdx.x;

    if (tid < KS * KS) ws[tid] = weight_space[tid];

    // Cooperative tile load with reflect padding (jnp 'reflect': -1 -> 1, H -> H-2)
    #pragma unroll
    for (int i = tid; i < TILE_H * TILE_W; i += BX * BY) {
        int ty = i / TILE_W;
        int tx = i - ty * TILE_W;
        int gy = by + ty - PAD;
        int gx = bx + tx - PAD;
        gy = (gy < 0) ? -gy : ((gy >= H) ? (2 * H - 2 - gy) : gy);
        gx = (gx < 0) ? -gx : ((gx >= W) ? (2 * W - 2 - gx) : gx);
        tile[ty][tx] = xp[gy * W + gx];
    }
    __syncthreads();

    const float c = tile[threadIdx.y + PAD][threadIdx.x + PAD];

    float num = 0.0f;
    float den = 0.0f;
    #pragma unroll
    for (int i = 0; i < KS; i++) {
        #pragma unroll
        for (int j = 0; j < KS; j++) {
            float p = tile[threadIdx.y + i][threadIdx.x + j];
            float d = p - c;
            // wd = exp(-d^2 / (2*SIGMA_DENSITY^2)), SIGMA_DENSITY = 1
            float wd = __expf(-0.5f * d * d) * ws[i * KS + j];
            num = fmaf(wd, p, num);
            den += wd;
        }
    }

    out[(size_t)plane * H * W + (by + threadIdx.y) * W + (bx + threadIdx.x)] = num / den;
}

extern "C" void kernel_launch(void* const* d_in, const int* in_sizes, int n_in,
                              void* d_out, int out_size)
{
    const float* x  = (const float*)d_in[0];        // [4,3,512,512] fp32
    const float* ws = (const float*)d_in[1];        // [5,5] fp32
    float* out = (float*)d_out;

    dim3 block(BX, BY);
    dim3 grid(W / BX, H / BY, NPLANES);             // 16 x 64 x 12 = 12288 CTAs
    bilateral_kernel<<<grid, block>>>(x, ws, out);
}